// round 16
// baseline (speedup 1.0000x reference)
#include <cuda_runtime.h>
#include <cuda_fp16.h>
#include <cstdint>

#define Bq 4
#define Sq 2048
#define Dq 1024
#define Hq 16
#define HDq 64
#define BSq (Bq*Sq)   // 8192
#define DD  (Dq*Dq)

// ---------------- scratch (__device__ globals; no allocs allowed) ----------
__device__ __half g_x16[3*BSq*Dq];    // activation fp16 (q,k,v)
__device__ __half g_w16[4*DD];        // all weights single fp16 (q,k,v,fc)
__device__ __half g_Q16[BSq*Dq];
__device__ __half g_K16[BSq*Dq];
__device__ __half g_V16[BSq*Dq];
__device__ __half g_A16[BSq*Dq];      // attention output fp16

__device__ __forceinline__ uint32_t smem_to_u32(const void* p) {
    uint32_t a;
    asm("{ .reg .u64 t; cvta.to.shared.u64 t, %1; cvt.u32.u64 %0, t; }"
        : "=r"(a) : "l"(p));
    return a;
}
__device__ __forceinline__ void cp16(uint32_t dst, const void* src) {
    asm volatile("cp.async.cg.shared.global [%0], [%1], 16;"
                 :: "r"(dst), "l"(src) : "memory");
}
__device__ __forceinline__ void cp_commit() {
    asm volatile("cp.async.commit_group;" ::: "memory");
}
template <int N>
__device__ __forceinline__ void cp_wait() {
    asm volatile("cp.async.wait_group %0;" :: "n"(N) : "memory");
}
__device__ __forceinline__ void ldsm_x4(uint32_t* r, uint32_t addr) {
    asm volatile("ldmatrix.sync.aligned.m8n8.x4.shared.b16 {%0,%1,%2,%3}, [%4];"
                 : "=r"(r[0]), "=r"(r[1]), "=r"(r[2]), "=r"(r[3]) : "r"(addr));
}
__device__ __forceinline__ void ldsm_x4_trans(uint32_t* r, uint32_t addr) {
    asm volatile("ldmatrix.sync.aligned.m8n8.x4.trans.shared.b16 {%0,%1,%2,%3}, [%4];"
                 : "=r"(r[0]), "=r"(r[1]), "=r"(r[2]), "=r"(r[3]) : "r"(addr));
}
__device__ __forceinline__ void mma_f16(float* d, const uint32_t* a, const uint32_t* b) {
    asm volatile(
        "mma.sync.aligned.m16n8k16.row.col.f32.f16.f16.f32 "
        "{%0,%1,%2,%3}, {%4,%5,%6,%7}, {%8,%9}, {%0,%1,%2,%3};"
        : "+f"(d[0]), "+f"(d[1]), "+f"(d[2]), "+f"(d[3])
        : "r"(a[0]), "r"(a[1]), "r"(a[2]), "r"(a[3]), "r"(b[0]), "r"(b[1]));
}
__device__ __forceinline__ uint32_t pack_h16(float x, float y) {
    __half2 v = __floats2half2_rn(x, y);
    return *(uint32_t*)&v;
}

// ---------------------------------------------------------------------------
// Converts: fp32 -> fp16
// ---------------------------------------------------------------------------
__global__ void conv_act16(const float4* __restrict__ q, const float4* __restrict__ k,
                           const float4* __restrict__ v,
                           __half2* __restrict__ x16, int n4)
{
    const int z = blockIdx.y;
    const float4* x = (z == 0) ? q : (z == 1) ? k : v;
    int i = blockIdx.x * blockDim.x + threadIdx.x;
    if (i >= n4) return;
    float4 w = x[i];
    __half2* o = x16 + (size_t)z * n4 * 2;
    o[i*2 + 0] = __floats2half2_rn(w.x, w.y);
    o[i*2 + 1] = __floats2half2_rn(w.z, w.w);
}

__global__ void conv_w16(const float4* __restrict__ w0, const float4* __restrict__ w1,
                         const float4* __restrict__ w2, const float4* __restrict__ w3,
                         __half2* __restrict__ w16, int n4)
{
    const int z = blockIdx.y;
    const float4* x = (z == 0) ? w0 : (z == 1) ? w1 : (z == 2) ? w2 : w3;
    int i = blockIdx.x * blockDim.x + threadIdx.x;
    if (i >= n4) return;
    float4 v = x[i];
    __half2* o = w16 + (size_t)z * n4 * 2;
    o[i*2 + 0] = __floats2half2_rn(v.x, v.y);
    o[i*2 + 1] = __floats2half2_rn(v.z, v.w);
}

// ---------------------------------------------------------------------------
// fp16 HMMA GEMM, single term. K-chunk 64 (4 k16 steps per barrier interval),
// 3-stage cp.async, ONE barrier per chunk. CTA 128x128, 8 warps (64x32 tile).
// Batched over blockIdx.z (activation slab / weight slab / bias / output).
// Accumulation order identical to the 32-chunk version -> bit-exact results.
// ---------------------------------------------------------------------------
#define GSTRIDE 72                   // 64 el + 8 pad (fp16)
#define GMAT    (128*GSTRIDE*2)      // 18432 B
#define GSTG    (2*GMAT)             // 36864 B per stage (A + W)
#define GSMEM   (3*GSTG)             // 110592 B
#define NCHUNK  (Dq/64)              // 16

template<bool F32OUT>
__global__ __launch_bounds__(256, 2)
void gemm16_kernel(const __half* __restrict__ Ab,
                   const __half* __restrict__ Wb,
                   const float* __restrict__ bias0, const float* __restrict__ bias1,
                   const float* __restrict__ bias2,
                   float* __restrict__ C,
                   __half* __restrict__ H0, __half* __restrict__ H1,
                   __half* __restrict__ H2)
{
    extern __shared__ char smem[];
    const uint32_t smem_base = smem_to_u32(smem);
    const int tid  = threadIdx.x;
    const int lane = tid & 31;
    const int wid  = tid >> 5;
    const int z  = blockIdx.z;
    const int m0 = blockIdx.y * 128;
    const int n0 = blockIdx.x * 128;
    const int wm0 = (wid & 1) * 64;
    const int wn0 = (wid >> 1) * 32;

    const float* bias = (z == 0) ? bias0 : (z == 1) ? bias1 : bias2;
    __half* H = (z == 0) ? H0 : (z == 1) ? H1 : H2;

    // cp.async: 2 threads per row, each 64B (4 x cp16) per matrix
    const int row0 = tid >> 1, kq0 = (tid & 1) * 32;

    const __half* gA = Ab + (size_t)z * BSq * Dq + (size_t)m0 * Dq;
    const __half* gW = Wb + (size_t)z * DD + (size_t)n0 * Dq;

    float acc[4][4][4];
    #pragma unroll
    for (int i = 0; i < 4; i++)
        #pragma unroll
        for (int j = 0; j < 4; j++)
            #pragma unroll
            for (int r = 0; r < 4; r++) acc[i][j][r] = 0.f;

    auto issue = [&](int c, int s) {
        const int k0 = c * 64;
        uint32_t sb = smem_base + s * GSTG;
        uint32_t d0 = (uint32_t)((row0 * GSTRIDE + kq0) * 2);
        size_t g0 = (size_t)row0 * Dq + k0 + kq0;
        #pragma unroll
        for (int u = 0; u < 4; u++) {
            cp16(sb + 0*GMAT + d0 + u*16, gA + g0 + u*8);
            cp16(sb + 1*GMAT + d0 + u*16, gW + g0 + u*8);
        }
    };

    issue(0, 0); cp_commit();
    issue(1, 1); cp_commit();

    const int a_r = wm0 + (lane & 15);
    const int a_c = (lane >> 4) * 8;
    const int b_r = wn0 + (lane & 7) + ((lane >> 4) << 3);
    const int b_c = ((lane >> 3) & 1) * 8;

    int s = 0;
    for (int c = 0; c < NCHUNK; c++) {
        if (c + 1 < NCHUNK) cp_wait<1>(); else cp_wait<0>();
        __syncthreads();          // all warps done with stage (c-1)%3; stage c%3 visible
        if (c + 2 < NCHUNK) {     // refill the stage consumed at chunk c-1
            int s2 = s + 2; if (s2 >= 3) s2 -= 3;
            issue(c + 2, s2);
            cp_commit();
        }

        const uint32_t sb = smem_base + s * GSTG;
        const uint32_t aB = sb, wB = sb + GMAT;

        #pragma unroll
        for (int kk = 0; kk < 4; kk++) {
            const int k16 = kk * 16;
            uint32_t b0[2][4];
            #pragma unroll
            for (int jj = 0; jj < 2; jj++) {
                uint32_t off = (uint32_t)((b_r + jj*16) * (GSTRIDE*2) + (k16 + b_c) * 2);
                ldsm_x4(b0[jj], wB + off);
            }
            #pragma unroll
            for (int i = 0; i < 4; i++) {
                uint32_t a[4];
                uint32_t off = (uint32_t)((a_r + i*16) * (GSTRIDE*2) + (k16 + a_c) * 2);
                ldsm_x4(a, aB + off);
                #pragma unroll
                for (int j = 0; j < 4; j++)
                    mma_f16(acc[i][j], a, &b0[j >> 1][(j & 1) * 2]);
            }
        }
        if (++s >= 3) s = 0;
    }

    // epilogue
    const int g = lane >> 2, t = lane & 3;
    #pragma unroll
    for (int j = 0; j < 4; j++) {
        const int col = n0 + wn0 + j*8 + t*2;
        const float bx = __ldg(&bias[col]);
        const float by = __ldg(&bias[col + 1]);
        #pragma unroll
        for (int i = 0; i < 4; i++) {
            const int r0 = m0 + wm0 + i*16 + g;
            float v0x = acc[i][j][0] + bx, v0y = acc[i][j][1] + by;
            float v1x = acc[i][j][2] + bx, v1y = acc[i][j][3] + by;
            if (F32OUT) {
                float2 w0, w1;
                w0.x = v0x; w0.y = v0y; w1.x = v1x; w1.y = v1y;
                *(float2*)&C[(size_t)r0 * Dq + col] = w0;
                *(float2*)&C[(size_t)(r0 + 8) * Dq + col] = w1;
            } else {
                *(__half2*)&H[(size_t)r0 * Dq + col] = __floats2half2_rn(v0x, v0y);
                *(__half2*)&H[(size_t)(r0+8) * Dq + col] = __floats2half2_rn(v1x, v1y);
            }
        }
    }
}

// ---------------------------------------------------------------------------
// FA2 HMMA attention (unchanged from round 15; verified correct).
// fp16 internals, fp32 accum; m16 x n64 warp tile, 256 thr, 2 CTAs/SM.
// 3-stage cp.async KV pipeline, ONE barrier per tile.
// ---------------------------------------------------------------------------
#define AST 72
#define AT_TILE  (64*AST*2)          // 9216 B per matrix
#define AT_STAGE (2*AT_TILE)         // 18432 B per stage (K+V)
#define QBYTES   (128*AST*2)         // 18432 B
#define KVOFF    QBYTES
#define AT_SMEM  (KVOFF + 3*AT_STAGE)  // 73728 B

__global__ __launch_bounds__(256, 2)
void attn_mma_kernel(const __half* __restrict__ Q16, const __half* __restrict__ K16,
                     const __half* __restrict__ V16, __half* __restrict__ A16)
{
    extern __shared__ char smem[];
    const uint32_t sbase = smem_to_u32(smem);
    const int tid = threadIdx.x, lane = tid & 31, wid = tid >> 5;
    const int bh = blockIdx.y, b = bh >> 4, h = bh & 15;
    const int q0 = blockIdx.x * 128;
    const int g = lane >> 2, t4 = lane & 3;

    // ---- stage Q (scaled by 1/8, exact in fp16) ----
    {
        __half* sQ = (__half*)smem;
        const int row = tid >> 1, halfo = (tid & 1) * 32;
        const __half2 sc = __floats2half2_rn(0.125f, 0.125f);
        size_t gq = ((size_t)(b*Sq) + q0 + row) * Dq + h*HDq + halfo;
        #pragma unroll
        for (int u = 0; u < 4; u++) {
            uint4 x4 = *(const uint4*)(Q16 + gq + u*8);
            __half2* p = (__half2*)&x4;
            #pragma unroll
            for (int e = 0; e < 4; e++) p[e] = __hmul2(p[e], sc);
            *(uint4*)&sQ[row*AST + halfo + u*8] = x4;
        }
    }

    // KV cp.async issue: each thread 4 x cp16 (2 per matrix)
    const int krow = tid >> 2, kd0 = (tid & 3) * 16;
    const size_t kvrowbase = (size_t)(b*Sq) * Dq + h*HDq + (size_t)krow * Dq + kd0;
    const uint32_t so = (uint32_t)((krow*AST + kd0) * 2);

    auto issue_kv = [&](int tile, int s) {
        size_t gk = kvrowbase + (size_t)tile * 64 * Dq;
        uint32_t sb = sbase + KVOFF + s * AT_STAGE;
        cp16(sb + 0*AT_TILE + so,      K16 + gk);
        cp16(sb + 0*AT_TILE + so + 16, K16 + gk + 8);
        cp16(sb + 1*AT_TILE + so,      V16 + gk);
        cp16(sb + 1*AT_TILE + so + 16, V16 + gk + 8);
    };

    issue_kv(0, 0); cp_commit();
    issue_kv(1, 1); cp_commit();
    __syncthreads();   // Q staged (orders smem Q writes vs ldsm reads)

    // Q fragments -> registers (16 regs)
    uint32_t qf[4][4];
    {
        uint32_t rowoff = (uint32_t)(((wid*16 + (lane & 15))*AST + (lane >> 4)*8) * 2);
        #pragma unroll
        for (int kk = 0; kk < 4; kk++)
            ldsm_x4(qf[kk], sbase + rowoff + kk*32);
    }

    float m0 = -1e30f, m1 = -1e30f, l0 = 0.f, l1 = 0.f;
    float o[8][4];
    #pragma unroll
    for (int j = 0; j < 8; j++)
        #pragma unroll
        for (int r = 0; r < 4; r++) o[j][r] = 0.f;

    const uint32_t kb_row = (lane & 7) + ((lane >> 4) & 1) * 8;
    const uint32_t kb_col = ((lane >> 3) & 1) * 8;
    const uint32_t vb_row = (lane & 7) + ((lane >> 3) & 1) * 8;
    const uint32_t vb_col = ((lane >> 4) & 1) * 8;

    const int NT = Sq/64;
    int s = 0;
    for (int tile = 0; tile < NT; tile++) {
        if (tile + 1 < NT) cp_wait<1>(); else cp_wait<0>();
        __syncthreads();
        if (tile + 2 < NT) {
            int s2 = s + 2; if (s2 >= 3) s2 -= 3;
            issue_kv(tile + 2, s2);
            cp_commit();
        }

        const uint32_t sb = sbase + KVOFF + s * AT_STAGE;
        const uint32_t oK = sb, oV = sb + AT_TILE;

        // ---- S = (Q/8) K^T ----
        float sAcc[8][4];
        #pragma unroll
        for (int j = 0; j < 8; j++)
            #pragma unroll
            for (int r = 0; r < 4; r++) sAcc[j][r] = 0.f;
        #pragma unroll
        for (int kk = 0; kk < 4; kk++) {
            #pragma unroll
            for (int jj = 0; jj < 4; jj++) {
                uint32_t off = (uint32_t)(((jj*16 + kb_row)*AST + kk*16 + kb_col) * 2);
                uint32_t kf[4];
                ldsm_x4(kf, oK + off);
                mma_f16(sAcc[2*jj],   qf[kk], &kf[0]);
                mma_f16(sAcc[2*jj+1], qf[kk], &kf[2]);
            }
        }

        // ---- online softmax ----
        float mx0 = -1e30f, mx1 = -1e30f;
        #pragma unroll
        for (int j = 0; j < 8; j++) {
            mx0 = fmaxf(mx0, fmaxf(sAcc[j][0], sAcc[j][1]));
            mx1 = fmaxf(mx1, fmaxf(sAcc[j][2], sAcc[j][3]));
        }
        mx0 = fmaxf(mx0, __shfl_xor_sync(0xffffffffu, mx0, 1));
        mx0 = fmaxf(mx0, __shfl_xor_sync(0xffffffffu, mx0, 2));
        mx1 = fmaxf(mx1, __shfl_xor_sync(0xffffffffu, mx1, 1));
        mx1 = fmaxf(mx1, __shfl_xor_sync(0xffffffffu, mx1, 2));
        float mn0 = fmaxf(m0, mx0), mn1 = fmaxf(m1, mx1);
        float c0 = __expf(m0 - mn0), c1 = __expf(m1 - mn1);
        if (!__all_sync(0xffffffffu, (m0 == mn0) & (m1 == mn1))) {
            #pragma unroll
            for (int j = 0; j < 8; j++) {
                o[j][0] *= c0; o[j][1] *= c0;
                o[j][2] *= c1; o[j][3] *= c1;
            }
        }
        float sum0 = 0.f, sum1 = 0.f;

        // ---- exp + pack + PV (interleaved per key-block) ----
        #pragma unroll
        for (int kk = 0; kk < 4; kk++) {
            float* s0 = sAcc[2*kk];
            float* s1 = sAcc[2*kk+1];
            s0[0] = __expf(s0[0] - mn0); sum0 += s0[0];
            s0[1] = __expf(s0[1] - mn0); sum0 += s0[1];
            s0[2] = __expf(s0[2] - mn1); sum1 += s0[2];
            s0[3] = __expf(s0[3] - mn1); sum1 += s0[3];
            s1[0] = __expf(s1[0] - mn0); sum0 += s1[0];
            s1[1] = __expf(s1[1] - mn0); sum0 += s1[1];
            s1[2] = __expf(s1[2] - mn1); sum1 += s1[2];
            s1[3] = __expf(s1[3] - mn1); sum1 += s1[3];

            uint32_t pf[4];
            pf[0] = pack_h16(s0[0], s0[1]);
            pf[1] = pack_h16(s0[2], s0[3]);
            pf[2] = pack_h16(s1[0], s1[1]);
            pf[3] = pack_h16(s1[2], s1[3]);

            #pragma unroll
            for (int jj = 0; jj < 4; jj++) {
                uint32_t off = (uint32_t)(((kk*16 + vb_row)*AST + jj*16 + vb_col) * 2);
                uint32_t vf[4];
                ldsm_x4_trans(vf, oV + off);
                mma_f16(o[2*jj],   pf, &vf[0]);
                mma_f16(o[2*jj+1], pf, &vf[2]);
            }
        }

        sum0 += __shfl_xor_sync(0xffffffffu, sum0, 1);
        sum0 += __shfl_xor_sync(0xffffffffu, sum0, 2);
        sum1 += __shfl_xor_sync(0xffffffffu, sum1, 1);
        sum1 += __shfl_xor_sync(0xffffffffu, sum1, 2);
        m0 = mn0; m1 = mn1;
        l0 = l0 * c0 + sum0;
        l1 = l1 * c1 + sum1;

        if (++s >= 3) s = 0;
    }

    // ---- epilogue: normalize, write fp16 ----
    float inv0 = 1.0f / l0, inv1 = 1.0f / l1;
    const int row0 = q0 + wid*16 + g;
    size_t ob0 = ((size_t)(b*Sq) + row0) * Dq + h*HDq;
    size_t ob1 = ob0 + (size_t)8 * Dq;
    #pragma unroll
    for (int j = 0; j < 8; j++) {
        const int c = j*8 + t4*2;
        *(__half2*)&A16[ob0 + c] = __floats2half2_rn(o[j][0] * inv0, o[j][1] * inv0);
        *(__half2*)&A16[ob1 + c] = __floats2half2_rn(o[j][2] * inv1, o[j][3] * inv1);
    }
}

// ---------------------------------------------------------------------------
extern "C" void kernel_launch(void* const* d_in, const int* in_sizes, int n_in,
                              void* d_out, int out_size)
{
    const float* q   = (const float*)d_in[0];
    const float* k   = (const float*)d_in[1];
    const float* v   = (const float*)d_in[2];
    const float* w_q = (const float*)d_in[3];
    const float* b_q = (const float*)d_in[4];
    const float* w_k = (const float*)d_in[5];
    const float* b_k = (const float*)d_in[6];
    const float* w_v = (const float*)d_in[7];
    const float* b_v = (const float*)d_in[8];
    const float* w_fc= (const float*)d_in[9];
    const float* b_fc= (const float*)d_in[10];
    float* out = (float*)d_out;

    __half *x16, *w16, *Q16, *K16, *V16, *A16;
    cudaGetSymbolAddress((void**)&x16, g_x16);
    cudaGetSymbolAddress((void**)&w16, g_w16);
    cudaGetSymbolAddress((void**)&Q16, g_Q16);
    cudaGetSymbolAddress((void**)&K16, g_K16);
    cudaGetSymbolAddress((void**)&V16, g_V16);
    cudaGetSymbolAddress((void**)&A16, g_A16);

    cudaFuncSetAttribute(gemm16_kernel<false>,
                         cudaFuncAttributeMaxDynamicSharedMemorySize, GSMEM);
    cudaFuncSetAttribute(gemm16_kernel<true>,
                         cudaFuncAttributeMaxDynamicSharedMemorySize, GSMEM);
    cudaFuncSetAttribute(attn_mma_kernel,
                         cudaFuncAttributeMaxDynamicSharedMemorySize, AT_SMEM);

    const int actN4 = BSq*Dq/4;
    const int wN4   = DD/4;
    dim3 sblk(256);

    // weight converts (all 4 -> single fp16), one launch
    conv_w16<<<dim3((wN4 + 255)/256, 4), sblk>>>(
        (const float4*)w_q, (const float4*)w_k, (const float4*)w_v, (const float4*)w_fc,
        (__half2*)w16, wN4);

    // activation converts, one launch
    conv_act16<<<dim3((actN4 + 255)/256, 3), sblk>>>(
        (const float4*)q, (const float4*)k, (const float4*)v, (__half2*)x16, actN4);

    // Q/K/V projections: fp16 x fp16 single term -> fp16 (K-chunk 64)
    gemm16_kernel<false><<<dim3(Dq/128, BSq/128, 3), 256, GSMEM>>>(
        x16, w16, b_q, b_k, b_v, nullptr, Q16, K16, V16);

    // attention (3-stage pipeline, 1 barrier/tile)
    attn_mma_kernel<<<dim3(Sq/128, Bq*Hq), 256, AT_SMEM>>>(Q16, K16, V16, A16);

    // fc projection: fp16 x fp16 single term -> fp32 out
    gemm16_kernel<true><<<dim3(Dq/128, BSq/128, 1), 256, GSMEM>>>(
        A16, w16 + 3*DD, b_fc, b_fc, b_fc, out, nullptr, nullptr, nullptr);
}

// round 17
// speedup vs baseline: 1.1272x; 1.1272x over previous
#include <cuda_runtime.h>
#include <cuda_fp16.h>
#include <cstdint>

#define Bq 4
#define Sq 2048
#define Dq 1024
#define Hq 16
#define HDq 64
#define BSq (Bq*Sq)   // 8192
#define DD  (Dq*Dq)

// ---------------- scratch (__device__ globals; no allocs allowed) ----------
__device__ __half g_x16[3*BSq*Dq];    // activation fp16 (q,k,v)
__device__ __half g_w16[4*DD];        // all weights single fp16 (q,k,v,fc)
__device__ __half g_Q16[BSq*Dq];
__device__ __half g_K16[BSq*Dq];
__device__ __half g_V16[BSq*Dq];
__device__ __half g_A16[BSq*Dq];      // attention output fp16

__device__ __forceinline__ uint32_t smem_to_u32(const void* p) {
    uint32_t a;
    asm("{ .reg .u64 t; cvta.to.shared.u64 t, %1; cvt.u32.u64 %0, t; }"
        : "=r"(a) : "l"(p));
    return a;
}
__device__ __forceinline__ void cp16(uint32_t dst, const void* src) {
    asm volatile("cp.async.cg.shared.global [%0], [%1], 16;"
                 :: "r"(dst), "l"(src) : "memory");
}
__device__ __forceinline__ void cp_commit() {
    asm volatile("cp.async.commit_group;" ::: "memory");
}
template <int N>
__device__ __forceinline__ void cp_wait() {
    asm volatile("cp.async.wait_group %0;" :: "n"(N) : "memory");
}
__device__ __forceinline__ void ldsm_x4(uint32_t* r, uint32_t addr) {
    asm volatile("ldmatrix.sync.aligned.m8n8.x4.shared.b16 {%0,%1,%2,%3}, [%4];"
                 : "=r"(r[0]), "=r"(r[1]), "=r"(r[2]), "=r"(r[3]) : "r"(addr));
}
__device__ __forceinline__ void ldsm_x4_trans(uint32_t* r, uint32_t addr) {
    asm volatile("ldmatrix.sync.aligned.m8n8.x4.trans.shared.b16 {%0,%1,%2,%3}, [%4];"
                 : "=r"(r[0]), "=r"(r[1]), "=r"(r[2]), "=r"(r[3]) : "r"(addr));
}
__device__ __forceinline__ void mma_f16(float* d, const uint32_t* a, const uint32_t* b) {
    asm volatile(
        "mma.sync.aligned.m16n8k16.row.col.f32.f16.f16.f32 "
        "{%0,%1,%2,%3}, {%4,%5,%6,%7}, {%8,%9}, {%0,%1,%2,%3};"
        : "+f"(d[0]), "+f"(d[1]), "+f"(d[2]), "+f"(d[3])
        : "r"(a[0]), "r"(a[1]), "r"(a[2]), "r"(a[3]), "r"(b[0]), "r"(b[1]));
}
__device__ __forceinline__ uint32_t pack_h16(float x, float y) {
    __half2 v = __floats2half2_rn(x, y);
    return *(uint32_t*)&v;
}

// ---------------------------------------------------------------------------
// Converts: fp32 -> fp16
// ---------------------------------------------------------------------------
__global__ void conv_act16(const float4* __restrict__ q, const float4* __restrict__ k,
                           const float4* __restrict__ v,
                           __half2* __restrict__ x16, int n4)
{
    const int z = blockIdx.y;
    const float4* x = (z == 0) ? q : (z == 1) ? k : v;
    int i = blockIdx.x * blockDim.x + threadIdx.x;
    if (i >= n4) return;
    float4 w = x[i];
    __half2* o = x16 + (size_t)z * n4 * 2;
    o[i*2 + 0] = __floats2half2_rn(w.x, w.y);
    o[i*2 + 1] = __floats2half2_rn(w.z, w.w);
}

__global__ void conv_w16(const float4* __restrict__ w0, const float4* __restrict__ w1,
                         const float4* __restrict__ w2, const float4* __restrict__ w3,
                         __half2* __restrict__ w16, int n4)
{
    const int z = blockIdx.y;
    const float4* x = (z == 0) ? w0 : (z == 1) ? w1 : (z == 2) ? w2 : w3;
    int i = blockIdx.x * blockDim.x + threadIdx.x;
    if (i >= n4) return;
    float4 v = x[i];
    __half2* o = w16 + (size_t)z * n4 * 2;
    o[i*2 + 0] = __floats2half2_rn(v.x, v.y);
    o[i*2 + 1] = __floats2half2_rn(v.z, v.w);
}

// ---------------------------------------------------------------------------
// fp16 HMMA GEMM, single term. K-chunk 32, 3-stage cp.async, ONE barrier
// per chunk. CTA 128x128, 8 warps (64x32 warp tile).
// Round 17: B fragments double-buffered across the two k16 steps so the
// kk=1 B loads overlap the kk=0 MMAs (ldsm latency off the critical path).
// ---------------------------------------------------------------------------
#define GSTRIDE 40
#define GMAT    (128*GSTRIDE*2)     // 10240 B
#define GSTG    (2*GMAT)            // per stage (A + W)
#define GSMEM   (3*GSTG)            // 61440 B
#define NCHUNK  (Dq/32)

template<bool F32OUT>
__global__ __launch_bounds__(256, 2)
void gemm16_kernel(const __half* __restrict__ Ab,
                   const __half* __restrict__ Wb,
                   const float* __restrict__ bias0, const float* __restrict__ bias1,
                   const float* __restrict__ bias2,
                   float* __restrict__ C,
                   __half* __restrict__ H0, __half* __restrict__ H1,
                   __half* __restrict__ H2)
{
    extern __shared__ char smem[];
    const uint32_t smem_base = smem_to_u32(smem);
    const int tid  = threadIdx.x;
    const int lane = tid & 31;
    const int wid  = tid >> 5;
    const int z  = blockIdx.z;
    const int m0 = blockIdx.y * 128;
    const int n0 = blockIdx.x * 128;
    const int wm0 = (wid & 1) * 64;
    const int wn0 = (wid >> 1) * 32;

    const float* bias = (z == 0) ? bias0 : (z == 1) ? bias1 : bias2;
    __half* H = (z == 0) ? H0 : (z == 1) ? H1 : H2;

    const int id0 = tid, id1 = tid + 256;
    const int row0 = id0 >> 2, kq0 = (id0 & 3) * 8;
    const int row1 = id1 >> 2, kq1 = (id1 & 3) * 8;

    const __half* gA = Ab + (size_t)z * BSq * Dq + (size_t)m0 * Dq;
    const __half* gW = Wb + (size_t)z * DD + (size_t)n0 * Dq;

    float acc[4][4][4];
    #pragma unroll
    for (int i = 0; i < 4; i++)
        #pragma unroll
        for (int j = 0; j < 4; j++)
            #pragma unroll
            for (int r = 0; r < 4; r++) acc[i][j][r] = 0.f;

    auto issue = [&](int c, int s) {
        const int k0 = c * 32;
        uint32_t sb = smem_base + s * GSTG;
        uint32_t d0 = (uint32_t)(row0 * (GSTRIDE*2) + kq0 * 2);
        uint32_t d1 = (uint32_t)(row1 * (GSTRIDE*2) + kq1 * 2);
        size_t s0 = (size_t)row0 * Dq + k0 + kq0;
        size_t s1 = (size_t)row1 * Dq + k0 + kq1;
        cp16(sb + 0*GMAT + d0, gA + s0);
        cp16(sb + 0*GMAT + d1, gA + s1);
        cp16(sb + 1*GMAT + d0, gW + s0);
        cp16(sb + 1*GMAT + d1, gW + s1);
    };

    issue(0, 0); cp_commit();
    issue(1, 1); cp_commit();

    const int a_r = wm0 + (lane & 15);
    const int a_c = (lane >> 4) * 8;
    const int b_r = wn0 + (lane & 7) + ((lane >> 4) << 3);
    const int b_c = ((lane >> 3) & 1) * 8;

    int s = 0;
    for (int c = 0; c < NCHUNK; c++) {
        if (c + 1 < NCHUNK) cp_wait<1>(); else cp_wait<0>();
        __syncthreads();          // all warps done with stage (c-1)%3; stage c%3 visible
        if (c + 2 < NCHUNK) {     // refill the stage consumed at chunk c-1
            int s2 = s + 2; if (s2 >= 3) s2 -= 3;
            issue(c + 2, s2);
            cp_commit();
        }

        const uint32_t sb = smem_base + s * GSTG;
        const uint32_t aB = sb, wB = sb + GMAT;

        // B fragments double-buffered across the two k16 steps
        uint32_t bf[2][2][4];
        #pragma unroll
        for (int jj = 0; jj < 2; jj++) {
            uint32_t off = (uint32_t)((b_r + jj*16) * (GSTRIDE*2) + b_c * 2);
            ldsm_x4(bf[0][jj], wB + off);
        }

        #pragma unroll
        for (int kk = 0; kk < 2; kk++) {
            const int k16 = kk * 16;
            #pragma unroll
            for (int i = 0; i < 4; i++) {
                uint32_t a[4];
                uint32_t off = (uint32_t)((a_r + i*16) * (GSTRIDE*2) + (k16 + a_c) * 2);
                ldsm_x4(a, aB + off);
                if (kk == 0 && i == 0) {
                    // prefetch kk=1 B fragments under the kk=0 MMAs
                    #pragma unroll
                    for (int jj = 0; jj < 2; jj++) {
                        uint32_t boff = (uint32_t)((b_r + jj*16) * (GSTRIDE*2) + (16 + b_c) * 2);
                        ldsm_x4(bf[1][jj], wB + boff);
                    }
                }
                #pragma unroll
                for (int j = 0; j < 4; j++)
                    mma_f16(acc[i][j], a, &bf[kk][j >> 1][(j & 1) * 2]);
            }
        }
        if (++s >= 3) s = 0;
    }

    // epilogue
    const int g = lane >> 2, t = lane & 3;
    #pragma unroll
    for (int j = 0; j < 4; j++) {
        const int col = n0 + wn0 + j*8 + t*2;
        const float bx = __ldg(&bias[col]);
        const float by = __ldg(&bias[col + 1]);
        #pragma unroll
        for (int i = 0; i < 4; i++) {
            const int r0 = m0 + wm0 + i*16 + g;
            float v0x = acc[i][j][0] + bx, v0y = acc[i][j][1] + by;
            float v1x = acc[i][j][2] + bx, v1y = acc[i][j][3] + by;
            if (F32OUT) {
                float2 w0, w1;
                w0.x = v0x; w0.y = v0y; w1.x = v1x; w1.y = v1y;
                *(float2*)&C[(size_t)r0 * Dq + col] = w0;
                *(float2*)&C[(size_t)(r0 + 8) * Dq + col] = w1;
            } else {
                *(__half2*)&H[(size_t)r0 * Dq + col] = __floats2half2_rn(v0x, v0y);
                *(__half2*)&H[(size_t)(r0+8) * Dq + col] = __floats2half2_rn(v1x, v1y);
            }
        }
    }
}

// ---------------------------------------------------------------------------
// FA2 HMMA attention (round-15 version, unchanged).
// fp16 internals, fp32 accum; m16 x n64 warp tile, 256 thr, 2 CTAs/SM.
// 3-stage cp.async KV pipeline, ONE barrier per tile.
// ---------------------------------------------------------------------------
#define AST 72
#define AT_TILE  (64*AST*2)          // 9216 B per matrix
#define AT_STAGE (2*AT_TILE)         // 18432 B per stage (K+V)
#define QBYTES   (128*AST*2)         // 18432 B
#define KVOFF    QBYTES
#define AT_SMEM  (KVOFF + 3*AT_STAGE)  // 73728 B

__global__ __launch_bounds__(256, 2)
void attn_mma_kernel(const __half* __restrict__ Q16, const __half* __restrict__ K16,
                     const __half* __restrict__ V16, __half* __restrict__ A16)
{
    extern __shared__ char smem[];
    const uint32_t sbase = smem_to_u32(smem);
    const int tid = threadIdx.x, lane = tid & 31, wid = tid >> 5;
    const int bh = blockIdx.y, b = bh >> 4, h = bh & 15;
    const int q0 = blockIdx.x * 128;
    const int g = lane >> 2, t4 = lane & 3;

    // ---- stage Q (scaled by 1/8, exact in fp16) ----
    {
        __half* sQ = (__half*)smem;
        const int row = tid >> 1, halfo = (tid & 1) * 32;
        const __half2 sc = __floats2half2_rn(0.125f, 0.125f);
        size_t gq = ((size_t)(b*Sq) + q0 + row) * Dq + h*HDq + halfo;
        #pragma unroll
        for (int u = 0; u < 4; u++) {
            uint4 x4 = *(const uint4*)(Q16 + gq + u*8);
            __half2* p = (__half2*)&x4;
            #pragma unroll
            for (int e = 0; e < 4; e++) p[e] = __hmul2(p[e], sc);
            *(uint4*)&sQ[row*AST + halfo + u*8] = x4;
        }
    }

    // KV cp.async issue: each thread 4 x cp16 (2 per matrix)
    const int krow = tid >> 2, kd0 = (tid & 3) * 16;
    const size_t kvrowbase = (size_t)(b*Sq) * Dq + h*HDq + (size_t)krow * Dq + kd0;
    const uint32_t so = (uint32_t)((krow*AST + kd0) * 2);

    auto issue_kv = [&](int tile, int s) {
        size_t gk = kvrowbase + (size_t)tile * 64 * Dq;
        uint32_t sb = sbase + KVOFF + s * AT_STAGE;
        cp16(sb + 0*AT_TILE + so,      K16 + gk);
        cp16(sb + 0*AT_TILE + so + 16, K16 + gk + 8);
        cp16(sb + 1*AT_TILE + so,      V16 + gk);
        cp16(sb + 1*AT_TILE + so + 16, V16 + gk + 8);
    };

    issue_kv(0, 0); cp_commit();
    issue_kv(1, 1); cp_commit();
    __syncthreads();   // Q staged (orders smem Q writes vs ldsm reads)

    // Q fragments -> registers (16 regs)
    uint32_t qf[4][4];
    {
        uint32_t rowoff = (uint32_t)(((wid*16 + (lane & 15))*AST + (lane >> 4)*8) * 2);
        #pragma unroll
        for (int kk = 0; kk < 4; kk++)
            ldsm_x4(qf[kk], sbase + rowoff + kk*32);
    }

    float m0 = -1e30f, m1 = -1e30f, l0 = 0.f, l1 = 0.f;
    float o[8][4];
    #pragma unroll
    for (int j = 0; j < 8; j++)
        #pragma unroll
        for (int r = 0; r < 4; r++) o[j][r] = 0.f;

    const uint32_t kb_row = (lane & 7) + ((lane >> 4) & 1) * 8;
    const uint32_t kb_col = ((lane >> 3) & 1) * 8;
    const uint32_t vb_row = (lane & 7) + ((lane >> 3) & 1) * 8;
    const uint32_t vb_col = ((lane >> 4) & 1) * 8;

    const int NT = Sq/64;
    int s = 0;
    for (int tile = 0; tile < NT; tile++) {
        if (tile + 1 < NT) cp_wait<1>(); else cp_wait<0>();
        __syncthreads();
        if (tile + 2 < NT) {
            int s2 = s + 2; if (s2 >= 3) s2 -= 3;
            issue_kv(tile + 2, s2);
            cp_commit();
        }

        const uint32_t sb = sbase + KVOFF + s * AT_STAGE;
        const uint32_t oK = sb, oV = sb + AT_TILE;

        // ---- S = (Q/8) K^T ----
        float sAcc[8][4];
        #pragma unroll
        for (int j = 0; j < 8; j++)
            #pragma unroll
            for (int r = 0; r < 4; r++) sAcc[j][r] = 0.f;
        #pragma unroll
        for (int kk = 0; kk < 4; kk++) {
            #pragma unroll
            for (int jj = 0; jj < 4; jj++) {
                uint32_t off = (uint32_t)(((jj*16 + kb_row)*AST + kk*16 + kb_col) * 2);
                uint32_t kf[4];
                ldsm_x4(kf, oK + off);
                mma_f16(sAcc[2*jj],   qf[kk], &kf[0]);
                mma_f16(sAcc[2*jj+1], qf[kk], &kf[2]);
            }
        }

        // ---- online softmax ----
        float mx0 = -1e30f, mx1 = -1e30f;
        #pragma unroll
        for (int j = 0; j < 8; j++) {
            mx0 = fmaxf(mx0, fmaxf(sAcc[j][0], sAcc[j][1]));
            mx1 = fmaxf(mx1, fmaxf(sAcc[j][2], sAcc[j][3]));
        }
        mx0 = fmaxf(mx0, __shfl_xor_sync(0xffffffffu, mx0, 1));
        mx0 = fmaxf(mx0, __shfl_xor_sync(0xffffffffu, mx0, 2));
        mx1 = fmaxf(mx1, __shfl_xor_sync(0xffffffffu, mx1, 1));
        mx1 = fmaxf(mx1, __shfl_xor_sync(0xffffffffu, mx1, 2));
        float mn0 = fmaxf(m0, mx0), mn1 = fmaxf(m1, mx1);
        float c0 = __expf(m0 - mn0), c1 = __expf(m1 - mn1);
        if (!__all_sync(0xffffffffu, (m0 == mn0) & (m1 == mn1))) {
            #pragma unroll
            for (int j = 0; j < 8; j++) {
                o[j][0] *= c0; o[j][1] *= c0;
                o[j][2] *= c1; o[j][3] *= c1;
            }
        }
        float sum0 = 0.f, sum1 = 0.f;

        // ---- exp + pack + PV (interleaved per key-block) ----
        #pragma unroll
        for (int kk = 0; kk < 4; kk++) {
            float* s0 = sAcc[2*kk];
            float* s1 = sAcc[2*kk+1];
            s0[0] = __expf(s0[0] - mn0); sum0 += s0[0];
            s0[1] = __expf(s0[1] - mn0); sum0 += s0[1];
            s0[2] = __expf(s0[2] - mn1); sum1 += s0[2];
            s0[3] = __expf(s0[3] - mn1); sum1 += s0[3];
            s1[0] = __expf(s1[0] - mn0); sum0 += s1[0];
            s1[1] = __expf(s1[1] - mn0); sum0 += s1[1];
            s1[2] = __expf(s1[2] - mn1); sum1 += s1[2];
            s1[3] = __expf(s1[3] - mn1); sum1 += s1[3];

            uint32_t pf[4];
            pf[0] = pack_h16(s0[0], s0[1]);
            pf[1] = pack_h16(s0[2], s0[3]);
            pf[2] = pack_h16(s1[0], s1[1]);
            pf[3] = pack_h16(s1[2], s1[3]);

            #pragma unroll
            for (int jj = 0; jj < 4; jj++) {
                uint32_t off = (uint32_t)(((kk*16 + vb_row)*AST + jj*16 + vb_col) * 2);
                uint32_t vf[4];
                ldsm_x4_trans(vf, oV + off);
                mma_f16(o[2*jj],   pf, &vf[0]);
                mma_f16(o[2*jj+1], pf, &vf[2]);
            }
        }

        sum0 += __shfl_xor_sync(0xffffffffu, sum0, 1);
        sum0 += __shfl_xor_sync(0xffffffffu, sum0, 2);
        sum1 += __shfl_xor_sync(0xffffffffu, sum1, 1);
        sum1 += __shfl_xor_sync(0xffffffffu, sum1, 2);
        m0 = mn0; m1 = mn1;
        l0 = l0 * c0 + sum0;
        l1 = l1 * c1 + sum1;

        if (++s >= 3) s = 0;
    }

    // ---- epilogue: normalize, write fp16 ----
    float inv0 = 1.0f / l0, inv1 = 1.0f / l1;
    const int row0 = q0 + wid*16 + g;
    size_t ob0 = ((size_t)(b*Sq) + row0) * Dq + h*HDq;
    size_t ob1 = ob0 + (size_t)8 * Dq;
    #pragma unroll
    for (int j = 0; j < 8; j++) {
        const int c = j*8 + t4*2;
        *(__half2*)&A16[ob0 + c] = __floats2half2_rn(o[j][0] * inv0, o[j][1] * inv0);
        *(__half2*)&A16[ob1 + c] = __floats2half2_rn(o[j][2] * inv1, o[j][3] * inv1);
    }
}

// ---------------------------------------------------------------------------
extern "C" void kernel_launch(void* const* d_in, const int* in_sizes, int n_in,
                              void* d_out, int out_size)
{
    const float* q   = (const float*)d_in[0];
    const float* k   = (const float*)d_in[1];
    const float* v   = (const float*)d_in[2];
    const float* w_q = (const float*)d_in[3];
    const float* b_q = (const float*)d_in[4];
    const float* w_k = (const float*)d_in[5];
    const float* b_k = (const float*)d_in[6];
    const float* w_v = (const float*)d_in[7];
    const float* b_v = (const float*)d_in[8];
    const float* w_fc= (const float*)d_in[9];
    const float* b_fc= (const float*)d_in[10];
    float* out = (float*)d_out;

    __half *x16, *w16, *Q16, *K16, *V16, *A16;
    cudaGetSymbolAddress((void**)&x16, g_x16);
    cudaGetSymbolAddress((void**)&w16, g_w16);
    cudaGetSymbolAddress((void**)&Q16, g_Q16);
    cudaGetSymbolAddress((void**)&K16, g_K16);
    cudaGetSymbolAddress((void**)&V16, g_V16);
    cudaGetSymbolAddress((void**)&A16, g_A16);

    cudaFuncSetAttribute(gemm16_kernel<false>,
                         cudaFuncAttributeMaxDynamicSharedMemorySize, GSMEM);
    cudaFuncSetAttribute(gemm16_kernel<true>,
                         cudaFuncAttributeMaxDynamicSharedMemorySize, GSMEM);
    cudaFuncSetAttribute(attn_mma_kernel,
                         cudaFuncAttributeMaxDynamicSharedMemorySize, AT_SMEM);

    const int actN4 = BSq*Dq/4;
    const int wN4   = DD/4;
    dim3 sblk(256);

    // weight converts (all 4 -> single fp16), one launch
    conv_w16<<<dim3((wN4 + 255)/256, 4), sblk>>>(
        (const float4*)w_q, (const float4*)w_k, (const float4*)w_v, (const float4*)w_fc,
        (__half2*)w16, wN4);

    // activation converts, one launch
    conv_act16<<<dim3((actN4 + 255)/256, 3), sblk>>>(
        (const float4*)q, (const float4*)k, (const float4*)v, (__half2*)x16, actN4);

    // Q/K/V projections: fp16 x fp16 single term -> fp16 (K-chunk 32)
    gemm16_kernel<false><<<dim3(Dq/128, BSq/128, 3), 256, GSMEM>>>(
        x16, w16, b_q, b_k, b_v, nullptr, Q16, K16, V16);

    // attention (3-stage pipeline, 1 barrier/tile)
    attn_mma_kernel<<<dim3(Sq/128, Bq*Hq), 256, AT_SMEM>>>(Q16, K16, V16, A16);

    // fc projection: fp16 x fp16 single term -> fp32 out
    gemm16_kernel<true><<<dim3(Dq/128, BSq/128, 1), 256, GSMEM>>>(
        A16, w16 + 3*DD, b_fc, b_fc, b_fc, out, nullptr, nullptr, nullptr);
}